// round 14
// baseline (speedup 1.0000x reference)
#include <cuda_runtime.h>
#include <math.h>
#include <stdint.h>
#include <limits.h>

#define BB 8
#define NN 1024
#define KK 20
#define BN (BB*NN)
#define VEPS 1e-6f

// ---------------- scratch (static __device__, no allocs) ----------------
__device__ __align__(16) float g_pd[(size_t)BB*NN*NN];     // 33.5 MB pairwise pd
__device__ int    g_idx[BN*KK];
__device__ float  g_xx[BN];
__device__ float  g_M[4*85*42];                             // combined weights
__device__ __align__(16) float g_uv[(size_t)BN*4*85*4];     // [pt][r][4], r<4*CO
__device__ float  g_x1[BN*21*3];
__device__ float  g_x2[BN*21*3];
__device__ float  g_x3[BN*42*3];
__device__ float  g_x4[BN*85*3];
__device__ double g_sumd[341];
__device__ double g_sumsqd[341];
__device__ float  g_mu[341];
__device__ float  g_sf[341];                                // sqrt(var+1e-5)
__device__ float  g_d5v[BB*3*NN];

// ---------------- fused prep: xx norms + combined weights + stat zeroing -------------
__global__ void prep_kernel(const float* __restrict__ X, int D,
                            const float* __restrict__ w, const float* __restrict__ dw,
                            int C, int CO) {
    int g = blockIdx.x*blockDim.x + threadIdx.x;
    if (g < BN) {
        const float* row = X + (size_t)g * D;
        float s = 0.f;
        for (int d = 0; d < D; d++) s = fmaf(row[d], row[d], s);
        g_xx[g] = s;
    }
    if (g < CO*C) {
        int o = g / C, c = g - o*C;
        float wa = w[o*2*C + c],  wb = w[o*2*C + C + c];
        float da = dw[o*2*C + c], db = dw[o*2*C + C + c];
        g_M[(0*CO+o)*C + c] = wa;
        g_M[(1*CO+o)*C + c] = __fsub_rn(wb, wa);
        g_M[(2*CO+o)*C + c] = da;
        g_M[(3*CO+o)*C + c] = __fsub_rn(db, da);
    }
    if (g < 341) { g_sumd[g] = 0.0; g_sumsqd[g] = 0.0; }
}

// ---------------- Gram v2: 128x64 tile, 8x4 register blocking, k-major smem ----------
__global__ __launch_bounds__(256) void gram_kernel(const float* __restrict__ X, int D) {
    __shared__ float As[16][132];
    __shared__ float Bs[16][68];
    int b  = blockIdx.z;
    int tn = blockIdx.y * 128;
    int tm = blockIdx.x * 64;
    int tid = threadIdx.x;
    const float* Xb = X + (size_t)b*NN*D;

    float acc[8][4];
    #pragma unroll
    for (int i = 0; i < 8; i++)
        #pragma unroll
        for (int j = 0; j < 4; j++) acc[i][j] = 0.f;

    int lk = tid & 15;
    int ls = tid >> 4;
    int ty = tid >> 4;
    int tx = tid & 15;

    for (int k0 = 0; k0 < D; k0 += 16) {
        int gk = k0 + lk;
        bool kv = gk < D;
        #pragma unroll
        for (int ss = 0; ss < 2; ss++) {
            int slot = ls + ss*16;
            int r0 = tn + slot*4;
            float4 v;
            v.x = kv ? Xb[(size_t)(r0+0)*D + gk] : 0.f;
            v.y = kv ? Xb[(size_t)(r0+1)*D + gk] : 0.f;
            v.z = kv ? Xb[(size_t)(r0+2)*D + gk] : 0.f;
            v.w = kv ? Xb[(size_t)(r0+3)*D + gk] : 0.f;
            *reinterpret_cast<float4*>(&As[lk][slot*4]) = v;
        }
        {
            int r0 = tm + ls*4;
            float4 v;
            v.x = kv ? Xb[(size_t)(r0+0)*D + gk] : 0.f;
            v.y = kv ? Xb[(size_t)(r0+1)*D + gk] : 0.f;
            v.z = kv ? Xb[(size_t)(r0+2)*D + gk] : 0.f;
            v.w = kv ? Xb[(size_t)(r0+3)*D + gk] : 0.f;
            *reinterpret_cast<float4*>(&Bs[lk][ls*4]) = v;
        }
        __syncthreads();
        #pragma unroll
        for (int k = 0; k < 16; k++) {
            float4 a0 = *reinterpret_cast<const float4*>(&As[k][ty*8]);
            float4 a1 = *reinterpret_cast<const float4*>(&As[k][ty*8+4]);
            float4 bv = *reinterpret_cast<const float4*>(&Bs[k][tx*4]);
            float a[8] = {a0.x,a0.y,a0.z,a0.w,a1.x,a1.y,a1.z,a1.w};
            float bb2[4] = {bv.x,bv.y,bv.z,bv.w};
            #pragma unroll
            for (int i = 0; i < 8; i++)
                #pragma unroll
                for (int j = 0; j < 4; j++)
                    acc[i][j] = fmaf(a[i], bb2[j], acc[i][j]);
        }
        __syncthreads();
    }
    size_t base = (size_t)b*NN*NN;
    int m0 = tm + tx*4;
    float xm[4];
    #pragma unroll
    for (int j = 0; j < 4; j++) xm[j] = g_xx[b*NN + m0 + j];
    #pragma unroll
    for (int i = 0; i < 8; i++) {
        int n = tn + ty*8 + i;
        float xn = g_xx[b*NN + n];
        float4 o;
        #pragma unroll
        for (int j = 0; j < 4; j++) {
            float inner = __fmul_rn(-2.f, acc[i][j]);
            float t = __fsub_rn(-xn, inner);
            ((float*)&o)[j] = __fsub_rn(t, xm[j]);
        }
        *reinterpret_cast<float4*>(&g_pd[base + (size_t)n*NN + m0]) = o;
    }
}

// ---------------- top-20 per row v4: warp-register selection ------------------------
// Keys (value<<32)|~index are all distinct and order by (value desc, index asc) —
// exactly jax.lax.top_k's tie rule. Each warp selects its local top-20 of 128 in
// registers; 160 candidates rank-merged in smem. Output order = key desc = identical
// to previous rank-sorted output.
__global__ __launch_bounds__(256) void topk_kernel() {
    __shared__ unsigned long long wk[8*KK];
    int bn = blockIdx.x, t = threadIdx.x;
    int w = t >> 5, lane = t & 31;
    const float4* row4 = reinterpret_cast<const float4*>(g_pd + (size_t)bn*NN);
    int base = w*128 + lane*4;
    float4 f = row4[base >> 2];
    unsigned long long key[4];
    #pragma unroll
    for (int j = 0; j < 4; j++) {
        uint32_t u = __float_as_uint(((const float*)&f)[j]);
        u = (u & 0x80000000u) ? ~u : (u | 0x80000000u);
        key[j] = ((unsigned long long)u << 32) | (uint32_t)(~(uint32_t)(base + j));
    }
    #pragma unroll 1
    for (int it = 0; it < KK; it++) {
        unsigned long long best = key[0];
        if (key[1] > best) best = key[1];
        if (key[2] > best) best = key[2];
        if (key[3] > best) best = key[3];
        #pragma unroll
        for (int off = 16; off; off >>= 1) {
            unsigned long long o = __shfl_xor_sync(0xffffffffu, best, off);
            if (o > best) best = o;
        }
        #pragma unroll
        for (int j = 0; j < 4; j++)
            if (key[j] == best) { key[j] = 0ull; wk[w*KK + it] = best; }
    }
    __syncthreads();
    if (t < 8*KK) {
        unsigned long long mykey = wk[t];
        int r = 0;
        for (int j = 0; j < 8*KK; j++) r += (wk[j] > mykey);
        if (r < KK) {
            int idx = (int)(~(uint32_t)mykey);
            g_idx[bn*KK + r] = idx;
        }
    }
}

// ---------------- per-point transform: g_uv[pt][r][0..2] = M[r] . X[pt][:, d] ---------
__global__ void transform_kernel(const float* __restrict__ X, int C, int CO) {
    extern __shared__ float sm[];
    int R = 4*CO;
    float* Ms = sm;
    float* Xs = sm + R*C;
    int t = threadIdx.x;
    int D3 = C*3;
    for (int i = t; i < R*C; i += 256) Ms[i] = g_M[i];
    int p0 = blockIdx.x * 16;
    for (int i = t; i < 16*D3; i += 256) Xs[i] = X[(size_t)p0*D3 + i];
    __syncthreads();
    for (int p = 0; p < 16; p++) {
        const float* xp = Xs + p*D3;
        for (int oi = t; oi < R*3; oi += 256) {
            int r = oi / 3, d = oi - r*3;
            const float* Mr = Ms + r*C;
            float acc = 0.f;
            for (int c = 0; c < C; c++) acc = fmaf(Mr[c], xp[c*3 + d], acc);
            g_uv[((size_t)(p0+p)*R + r)*4 + d] = acc;
        }
    }
}

// ---------------- mirrored norm helper: rounded squares, ascending adds --------------
__device__ __forceinline__ float mir_norm(float x, float y, float z) {
    float n2 = __fadd_rn(__fadd_rn(__fmul_rn(x,x), __fmul_rn(y,y)), __fmul_rn(z,z));
    return __fadd_rn(sqrtf(n2), VEPS);
}

// ---------------- BN stats over all edges (layers 1-4), Kahan fp32 + double atomics --
__global__ void statsA_kernel(int CO, int PTS) {
    int o = threadIdx.x;
    if (o >= CO) return;
    int R = 4*CO;
    int ptbase = (blockIdx.x * blockDim.y + threadIdx.y) * PTS;
    const float4* uvp = reinterpret_cast<const float4*>(g_uv);
    float s = 0.f, cs = 0.f, s2 = 0.f, cs2 = 0.f;
    for (int pp = 0; pp < PTS; pp++) {
        int pt = ptbase + pp;
        int b = pt >> 10;
        float4 v = uvp[(size_t)pt*R + CO + o];
        const int* nb = g_idx + pt*KK;
        for (int k = 0; k < KK; k++) {
            int j = b*NN + nb[k];
            float4 u = uvp[(size_t)j*R + o];
            float nrm = mir_norm(u.x + v.x, u.y + v.y, u.z + v.z);
            float y  = __fsub_rn(nrm, cs);
            float tt = __fadd_rn(s, y);
            cs = __fsub_rn(__fsub_rn(tt, s), y);
            s = tt;
            float q  = __fmul_rn(nrm, nrm);
            y  = __fsub_rn(q, cs2);
            tt = __fadd_rn(s2, y);
            cs2 = __fsub_rn(__fsub_rn(tt, s2), y);
            s2 = tt;
        }
    }
    atomicAdd(&g_sumd[o],   (double)s  - (double)cs);
    atomicAdd(&g_sumsqd[o], (double)s2 - (double)cs2);
}

__global__ void zero_stats() {
    int i = blockIdx.x*blockDim.x + threadIdx.x;
    if (i < 341) { g_sumd[i] = 0.0; g_sumsqd[i] = 0.0; }
}

__global__ void finalize_kernel(int CO, double inv_cnt) {
    int o = blockIdx.x*blockDim.x + threadIdx.x;
    if (o >= CO) return;
    double mu = g_sumd[o] * inv_cnt;
    double var = g_sumsqd[o] * inv_cnt - mu*mu;
    if (var < 0.0) var = 0.0;
    g_mu[o] = (float)mu;
    g_sf[o] = sqrtf(__fadd_rn((float)var, 1e-5f));
}

// ---------------- apply BN + VN-LeakyReLU + mean over k, mirrored ops ----------------
__global__ void passB_kernel(const float* __restrict__ gamma, const float* __restrict__ beta,
                             float* __restrict__ Xout, int CO) {
    int o = threadIdx.x;
    if (o >= CO) return;
    int R = 4*CO;
    int pt = blockIdx.x * blockDim.y + threadIdx.y;
    int b = pt >> 10;
    const float4* uvp = reinterpret_cast<const float4*>(g_uv);
    float4 v  = uvp[(size_t)pt*R + CO   + o];
    float4 dv = uvp[(size_t)pt*R + 3*CO + o];
    const int* nb = g_idx + pt*KK;
    float mu = g_mu[o], sf = g_sf[o], ga = gamma[o], be = beta[o];
    const float a1 = 0.2f, a2 = __fsub_rn(1.0f, 0.2f);
    float ax = 0.f, ay = 0.f, az = 0.f;
    for (int k = 0; k < KK; k++) {
        int j = b*NN + nb[k];
        float4 u  = uvp[(size_t)j*R + o];
        float4 du = uvp[(size_t)j*R + 2*CO + o];
        float px = u.x + v.x,  py = u.y + v.y,  pz = u.z + v.z;
        float dx = du.x + dv.x, dy = du.y + dv.y, dz = du.z + dv.z;
        float nrm = mir_norm(px, py, pz);
        float tbn = __fdiv_rn(__fsub_rn(nrm, mu), sf);
        float nbn = __fadd_rn(__fmul_rn(tbn, ga), be);
        float qx = __fmul_rn(__fdiv_rn(px, nrm), nbn);
        float qy = __fmul_rn(__fdiv_rn(py, nrm), nbn);
        float qz = __fmul_rn(__fdiv_rn(pz, nrm), nbn);
        float dot = __fadd_rn(__fadd_rn(__fmul_rn(qx,dx), __fmul_rn(qy,dy)), __fmul_rn(qz,dz));
        float ox, oy, oz;
        if (dot >= 0.f) { ox = qx; oy = qy; oz = qz; }
        else {
            float dsq = __fadd_rn(__fadd_rn(__fmul_rn(dx,dx), __fmul_rn(dy,dy)), __fmul_rn(dz,dz));
            float tt = __fdiv_rn(dot, __fadd_rn(dsq, VEPS));
            ox = __fsub_rn(qx, __fmul_rn(tt, dx));
            oy = __fsub_rn(qy, __fmul_rn(tt, dy));
            oz = __fsub_rn(qz, __fmul_rn(tt, dz));
        }
        ax = __fadd_rn(ax, __fadd_rn(__fmul_rn(a1,qx), __fmul_rn(a2,ox)));
        ay = __fadd_rn(ay, __fadd_rn(__fmul_rn(a1,qy), __fmul_rn(a2,oy)));
        az = __fadd_rn(az, __fadd_rn(__fmul_rn(a1,qz), __fmul_rn(a2,oz)));
    }
    float* op = Xout + ((size_t)pt*CO + o)*3;
    op[0] = __fdiv_rn(ax, 20.0f);
    op[1] = __fdiv_rn(ay, 20.0f);
    op[2] = __fdiv_rn(az, 20.0f);
}

// ---------------- layer 5 ----------------
__device__ __forceinline__ const float* cat_ptr(int pt, int c) {
    if (c < 21) return g_x1 + ((size_t)pt*21 + c)*3;
    if (c < 42) return g_x2 + ((size_t)pt*21 + (c-21))*3;
    if (c < 84) return g_x3 + ((size_t)pt*42 + (c-42))*3;
    return g_x4 + ((size_t)pt*85 + (c-84))*3;
}

// l5 GEMM v2 + folded dir row: virtual output channel 341 uses d5 weights and
// writes to g_d5v. Identical ascending-c FMA chains.
__global__ __launch_bounds__(256) void l5_gemm_kernel(const float* __restrict__ w5,
                                                      const float* __restrict__ d5,
                                                      float* __restrict__ out) {
    extern __shared__ float sm[];
    float* Ws = sm;               // [32][169]
    float* Cs = sm + 32*169;      // [169][96], col = d*32 + p
    int t = threadIdx.x;
    int ob = blockIdx.y * 32;
    int pb = blockIdx.x * 32;
    for (int i = t; i < 32*169; i += 256) {
        int o = i / 169, c = i - o*169;
        int og = ob + o;
        float wv = 0.f;
        if (og < 341) wv = w5[og*169 + c];
        else if (og == 341) wv = d5[c];
        Ws[i] = wv;
    }
    for (int i = t; i < 169*96; i += 256) {
        int c = i / 96, r = i - c*96;
        int d = r >> 5, p = r & 31;
        Cs[i] = cat_ptr(pb + p, c)[d];
    }
    __syncthreads();
    int wid = t >> 5, lane = t & 31;
    int b = pb >> 10;
    int nbase = pb & 1023;
    float acc[4][3];
    #pragma unroll
    for (int j = 0; j < 4; j++) { acc[j][0] = acc[j][1] = acc[j][2] = 0.f; }
    const float* w0p = Ws + (wid*4 + 0)*169;
    const float* w1p = Ws + (wid*4 + 1)*169;
    const float* w2p = Ws + (wid*4 + 2)*169;
    const float* w3p = Ws + (wid*4 + 3)*169;
    const float* cp = Cs + lane;
    for (int c = 0; c < 169; c++) {
        float x0 = cp[0], x1 = cp[32], x2 = cp[64];
        float wv0 = w0p[c], wv1 = w1p[c], wv2 = w2p[c], wv3 = w3p[c];
        acc[0][0] = fmaf(wv0, x0, acc[0][0]);
        acc[0][1] = fmaf(wv0, x1, acc[0][1]);
        acc[0][2] = fmaf(wv0, x2, acc[0][2]);
        acc[1][0] = fmaf(wv1, x0, acc[1][0]);
        acc[1][1] = fmaf(wv1, x1, acc[1][1]);
        acc[1][2] = fmaf(wv1, x2, acc[1][2]);
        acc[2][0] = fmaf(wv2, x0, acc[2][0]);
        acc[2][1] = fmaf(wv2, x1, acc[2][1]);
        acc[2][2] = fmaf(wv2, x2, acc[2][2]);
        acc[3][0] = fmaf(wv3, x0, acc[3][0]);
        acc[3][1] = fmaf(wv3, x1, acc[3][1]);
        acc[3][2] = fmaf(wv3, x2, acc[3][2]);
        cp += 96;
    }
    #pragma unroll
    for (int j = 0; j < 4; j++) {
        int og = ob + wid*4 + j;
        if (og < 341) {
            #pragma unroll
            for (int d = 0; d < 3; d++)
                out[(((size_t)b*341 + og)*3 + d)*NN + nbase + lane] = acc[j][d];
        } else if (og == 341) {
            #pragma unroll
            for (int d = 0; d < 3; d++)
                g_d5v[(b*3 + d)*NN + nbase + lane] = acc[j][d];
        }
    }
}

__global__ void l5_stats_kernel(const float* __restrict__ p) {
    int o = blockIdx.x, b = blockIdx.y, t = threadIdx.x;
    const float* base = p + ((size_t)b*341 + o)*3*NN;
    double s = 0.0, s2 = 0.0;
    for (int n = t; n < NN; n += 256) {
        float nrm = mir_norm(base[n], base[NN + n], base[2*NN + n]);
        s += (double)nrm; s2 = fma((double)nrm, (double)nrm, s2);
    }
    __shared__ double sh1[8], sh2[8];
    #pragma unroll
    for (int off = 16; off; off >>= 1) {
        s  += __shfl_down_sync(0xffffffffu, s,  off);
        s2 += __shfl_down_sync(0xffffffffu, s2, off);
    }
    if ((t & 31) == 0) { sh1[t >> 5] = s; sh2[t >> 5] = s2; }
    __syncthreads();
    if (t == 0) {
        double a = 0.0, a2 = 0.0;
        #pragma unroll
        for (int w = 0; w < 8; w++) { a += sh1[w]; a2 += sh2[w]; }
        atomicAdd(&g_sumd[o], a);
        atomicAdd(&g_sumsqd[o], a2);
    }
}

__global__ void l5_apply_kernel(float* __restrict__ p, const float* __restrict__ gamma,
                                const float* __restrict__ beta) {
    int o = blockIdx.x, b = blockIdx.y, t = threadIdx.x;
    float mu = g_mu[o], sf = g_sf[o], ga = gamma[o], be = beta[o];
    const float a1 = 0.2f, a2 = __fsub_rn(1.0f, 0.2f);
    float* base = p + ((size_t)b*341 + o)*3*NN;
    const float* db = g_d5v + b*3*NN;
    for (int n = t; n < NN; n += 256) {
        float x = base[n], y = base[NN + n], z = base[2*NN + n];
        float dx = db[n], dy = db[NN + n], dz = db[2*NN + n];
        float nrm = mir_norm(x, y, z);
        float tbn = __fdiv_rn(__fsub_rn(nrm, mu), sf);
        float nbn = __fadd_rn(__fmul_rn(tbn, ga), be);
        float qx = __fmul_rn(__fdiv_rn(x, nrm), nbn);
        float qy = __fmul_rn(__fdiv_rn(y, nrm), nbn);
        float qz = __fmul_rn(__fdiv_rn(z, nrm), nbn);
        float dot = __fadd_rn(__fadd_rn(__fmul_rn(qx,dx), __fmul_rn(qy,dy)), __fmul_rn(qz,dz));
        float ox, oy, oz;
        if (dot >= 0.f) { ox = qx; oy = qy; oz = qz; }
        else {
            float dsq = __fadd_rn(__fadd_rn(__fmul_rn(dx,dx), __fmul_rn(dy,dy)), __fmul_rn(dz,dz));
            float tt = __fdiv_rn(dot, __fadd_rn(dsq, VEPS));
            ox = __fsub_rn(qx, __fmul_rn(tt, dx));
            oy = __fsub_rn(qy, __fmul_rn(tt, dy));
            oz = __fsub_rn(qz, __fmul_rn(tt, dz));
        }
        base[n]      = __fadd_rn(__fmul_rn(a1,qx), __fmul_rn(a2,ox));
        base[NN+n]   = __fadd_rn(__fmul_rn(a1,qy), __fmul_rn(a2,oy));
        base[2*NN+n] = __fadd_rn(__fmul_rn(a1,qz), __fmul_rn(a2,oz));
    }
}

// ---------------- host orchestration ----------------
static void run_layer(const float* Xin, int C, int CO,
                      const float* w, const float* dw,
                      const float* gamma, const float* beta,
                      float* Xout) {
    int D = C*3;
    prep_kernel<<<BN/256, 256>>>(Xin, D, w, dw, C, CO);
    gram_kernel<<<dim3(16,8,8), 256>>>(Xin, D);
    topk_kernel<<<BN, 256>>>();
    int smem_t = (4*CO*C + 16*D) * 4;
    transform_kernel<<<BN/16, 256, smem_t>>>(Xin, C, CO);
    int COW = ((CO + 31)/32)*32;
    int PY = 256 / COW;
    dim3 blk(COW, PY);
    const int PTS = 8;
    statsA_kernel<<<BN/(PY*PTS), blk>>>(CO, PTS);
    finalize_kernel<<<(CO + 127)/128, 128>>>(CO, 1.0/((double)BN*KK));
    passB_kernel<<<BN/PY, blk>>>(gamma, beta, Xout, CO);
}

extern "C" void kernel_launch(void* const* d_in, const int* in_sizes, int n_in,
                              void* d_out, int out_size) {
    const float* x   = (const float*)d_in[0];
    const float* w1  = (const float*)d_in[1];
    const float* dd1 = (const float*)d_in[2];
    const float* gg1 = (const float*)d_in[3];
    const float* bb1 = (const float*)d_in[4];
    const float* w2  = (const float*)d_in[5];
    const float* dd2 = (const float*)d_in[6];
    const float* gg2 = (const float*)d_in[7];
    const float* bb2 = (const float*)d_in[8];
    const float* w3  = (const float*)d_in[9];
    const float* dd3 = (const float*)d_in[10];
    const float* gg3 = (const float*)d_in[11];
    const float* bb3 = (const float*)d_in[12];
    const float* w4  = (const float*)d_in[13];
    const float* dd4 = (const float*)d_in[14];
    const float* gg4 = (const float*)d_in[15];
    const float* bb4 = (const float*)d_in[16];
    const float* w5  = (const float*)d_in[17];
    const float* dd5 = (const float*)d_in[18];
    const float* gg5 = (const float*)d_in[19];
    const float* bb5 = (const float*)d_in[20];
    float* out = (float*)d_out;

    cudaFuncSetAttribute(transform_kernel, cudaFuncAttributeMaxDynamicSharedMemorySize, 70*1024);
    cudaFuncSetAttribute(l5_gemm_kernel,   cudaFuncAttributeMaxDynamicSharedMemorySize, 90*1024);

    float *px1, *px2, *px3, *px4;
    cudaGetSymbolAddress((void**)&px1, g_x1);
    cudaGetSymbolAddress((void**)&px2, g_x2);
    cudaGetSymbolAddress((void**)&px3, g_x3);
    cudaGetSymbolAddress((void**)&px4, g_x4);

    run_layer(x,   1,  21, w1, dd1, gg1, bb1, px1);
    run_layer(px1, 21, 21, w2, dd2, gg2, bb2, px2);
    run_layer(px2, 21, 42, w3, dd3, gg3, bb3, px3);
    run_layer(px3, 42, 85, w4, dd4, gg4, bb4, px4);

    // layer 5 (dir row folded into gemm as virtual channel 341)
    zero_stats<<<2, 256>>>();
    l5_gemm_kernel<<<dim3(BN/32, 11), 256, 86528>>>(w5, dd5, out);
    l5_stats_kernel<<<dim3(341, BB), 256>>>(out);
    finalize_kernel<<<(341 + 127)/128, 128>>>(341, 1.0/(double)BN);
    l5_apply_kernel<<<dim3(341, BB), 256>>>(out, gg5, bb5);
}

// round 16
// speedup vs baseline: 1.2852x; 1.2852x over previous
#include <cuda_runtime.h>
#include <math.h>
#include <stdint.h>
#include <limits.h>

#define BB 8
#define NN 1024
#define KK 20
#define BN (BB*NN)
#define VEPS 1e-6f

// ---------------- scratch (static __device__, no allocs) ----------------
__device__ __align__(16) float g_pd[(size_t)BB*NN*NN];     // 33.5 MB pairwise pd
__device__ int    g_idx[BN*KK];
__device__ float  g_xx[BN];
__device__ float  g_M[4*85*42];                             // combined weights
__device__ __align__(16) float g_uv[(size_t)BN*4*85*4];     // [pt][r][4], r<4*CO
__device__ float  g_x1[BN*21*3];
__device__ float  g_x2[BN*21*3];
__device__ float  g_x3[BN*42*3];
__device__ float  g_x4[BN*85*3];
__device__ double g_sumd[341];
__device__ double g_sumsqd[341];
__device__ float  g_mu[341];
__device__ float  g_sf[341];                                // sqrt(var+1e-5)
__device__ float  g_d5v[BB*3*NN];

// ---------------- fused prep: xx norms + combined weights + stat zeroing -------------
__global__ void prep_kernel(const float* __restrict__ X, int D,
                            const float* __restrict__ w, const float* __restrict__ dw,
                            int C, int CO) {
    int g = blockIdx.x*blockDim.x + threadIdx.x;
    if (g < BN) {
        const float* row = X + (size_t)g * D;
        float s = 0.f;
        for (int d = 0; d < D; d++) s = fmaf(row[d], row[d], s);
        g_xx[g] = s;
    }
    if (g < CO*C) {
        int o = g / C, c = g - o*C;
        float wa = w[o*2*C + c],  wb = w[o*2*C + C + c];
        float da = dw[o*2*C + c], db = dw[o*2*C + C + c];
        g_M[(0*CO+o)*C + c] = wa;
        g_M[(1*CO+o)*C + c] = __fsub_rn(wb, wa);
        g_M[(2*CO+o)*C + c] = da;
        g_M[(3*CO+o)*C + c] = __fsub_rn(db, da);
    }
    if (g < 341) { g_sumd[g] = 0.0; g_sumsqd[g] = 0.0; }
}

// ---------------- Gram v2: 128x64 tile, 8x4 register blocking, k-major smem ----------
__global__ __launch_bounds__(256) void gram_kernel(const float* __restrict__ X, int D) {
    __shared__ float As[16][132];
    __shared__ float Bs[16][68];
    int b  = blockIdx.z;
    int tn = blockIdx.y * 128;
    int tm = blockIdx.x * 64;
    int tid = threadIdx.x;
    const float* Xb = X + (size_t)b*NN*D;

    float acc[8][4];
    #pragma unroll
    for (int i = 0; i < 8; i++)
        #pragma unroll
        for (int j = 0; j < 4; j++) acc[i][j] = 0.f;

    int lk = tid & 15;
    int ls = tid >> 4;
    int ty = tid >> 4;
    int tx = tid & 15;

    for (int k0 = 0; k0 < D; k0 += 16) {
        int gk = k0 + lk;
        bool kv = gk < D;
        #pragma unroll
        for (int ss = 0; ss < 2; ss++) {
            int slot = ls + ss*16;
            int r0 = tn + slot*4;
            float4 v;
            v.x = kv ? Xb[(size_t)(r0+0)*D + gk] : 0.f;
            v.y = kv ? Xb[(size_t)(r0+1)*D + gk] : 0.f;
            v.z = kv ? Xb[(size_t)(r0+2)*D + gk] : 0.f;
            v.w = kv ? Xb[(size_t)(r0+3)*D + gk] : 0.f;
            *reinterpret_cast<float4*>(&As[lk][slot*4]) = v;
        }
        {
            int r0 = tm + ls*4;
            float4 v;
            v.x = kv ? Xb[(size_t)(r0+0)*D + gk] : 0.f;
            v.y = kv ? Xb[(size_t)(r0+1)*D + gk] : 0.f;
            v.z = kv ? Xb[(size_t)(r0+2)*D + gk] : 0.f;
            v.w = kv ? Xb[(size_t)(r0+3)*D + gk] : 0.f;
            *reinterpret_cast<float4*>(&Bs[lk][ls*4]) = v;
        }
        __syncthreads();
        #pragma unroll
        for (int k = 0; k < 16; k++) {
            float4 a0 = *reinterpret_cast<const float4*>(&As[k][ty*8]);
            float4 a1 = *reinterpret_cast<const float4*>(&As[k][ty*8+4]);
            float4 bv = *reinterpret_cast<const float4*>(&Bs[k][tx*4]);
            float a[8] = {a0.x,a0.y,a0.z,a0.w,a1.x,a1.y,a1.z,a1.w};
            float bb2[4] = {bv.x,bv.y,bv.z,bv.w};
            #pragma unroll
            for (int i = 0; i < 8; i++)
                #pragma unroll
                for (int j = 0; j < 4; j++)
                    acc[i][j] = fmaf(a[i], bb2[j], acc[i][j]);
        }
        __syncthreads();
    }
    size_t base = (size_t)b*NN*NN;
    int m0 = tm + tx*4;
    float xm[4];
    #pragma unroll
    for (int j = 0; j < 4; j++) xm[j] = g_xx[b*NN + m0 + j];
    #pragma unroll
    for (int i = 0; i < 8; i++) {
        int n = tn + ty*8 + i;
        float xn = g_xx[b*NN + n];
        float4 o;
        #pragma unroll
        for (int j = 0; j < 4; j++) {
            float inner = __fmul_rn(-2.f, acc[i][j]);
            float t = __fsub_rn(-xn, inner);
            ((float*)&o)[j] = __fsub_rn(t, xm[j]);
        }
        *reinterpret_cast<float4*>(&g_pd[base + (size_t)n*NN + m0]) = o;
    }
}

// ---------------- suffix scan over 256 bins (warp-shuffle, 2 barriers) ---------------
__device__ __forceinline__ void suffix_scan256(const uint32_t* hist, uint32_t* Ssum,
                                               uint32_t* wtot, int t, int lane, int w) {
    uint32_t x = hist[t];
    #pragma unroll
    for (int off = 1; off < 32; off <<= 1) {
        uint32_t y = __shfl_down_sync(0xffffffffu, x, off);
        if (lane + off < 32) x += y;
    }
    if (lane == 0) wtot[w] = x;
    __syncthreads();
    uint32_t add = 0;
    #pragma unroll
    for (int ww = 0; ww < 8; ww++) if (ww > w) add += wtot[ww];
    Ssum[t] = x + add;
    if (t == 0) Ssum[256] = 0;
    __syncthreads();
}

// ---------------- top-20 per row: radix level 1 + compacted levels 2-4 (FROZEN) ------
// Same SET as jax.lax.top_k, then rank-sorted (value desc, index asc) so downstream
// accumulation order matches the reference gather order exactly.
__global__ __launch_bounds__(256) void topk_kernel() {
    __shared__ uint32_t uval[NN];
    __shared__ uint32_t cu[NN];  __shared__ int ci[NN];
    __shared__ uint32_t du[NN];  __shared__ int di[NN];
    __shared__ uint32_t hist[256];
    __shared__ uint32_t Ssum[257];
    __shared__ uint32_t wtot[8];
    __shared__ uint32_t selu[KK]; __shared__ int seli[KK];
    __shared__ int selcnt, nc, nc2;
    __shared__ uint32_t selbin;

    int bn = blockIdx.x, t = threadIdx.x;
    int lane = t & 31, w = t >> 5;
    uint32_t lm = (1u << lane) - 1u;
    const float* row = g_pd + (size_t)bn*NN;
    if (t == 0) { selcnt = 0; nc = 0; }
    hist[t] = 0;
    __syncthreads();

    // ---- level 1 over all 1024 ----
    for (int i = t; i < NN; i += 256) {
        uint32_t u = __float_as_uint(row[i]);
        u = (u & 0x80000000u) ? ~u : (u | 0x80000000u);
        uval[i] = u;
        atomicAdd(&hist[u >> 24], 1u);
    }
    __syncthreads();
    suffix_scan256(hist, Ssum, wtot, t, lane, w);
    int need = KK;
    if (Ssum[t] >= (uint32_t)need && Ssum[t+1] < (uint32_t)need) selbin = t;
    __syncthreads();
    {
        uint32_t b = selbin;
        int nneed = need - (int)Ssum[b+1];
        for (int i = t; i < NN; i += 256) {
            uint32_t u = uval[i];
            uint32_t by = u >> 24;
            bool gt = by > b, eq = by == b;
            uint32_t mg = __ballot_sync(0xffffffffu, gt);
            uint32_t me = __ballot_sync(0xffffffffu, eq);
            int bg = 0, be = 0;
            if (lane == 0) {
                if (mg) bg = atomicAdd(&selcnt, __popc(mg));
                if (me) be = atomicAdd(&nc, __popc(me));
            }
            bg = __shfl_sync(0xffffffffu, bg, 0);
            be = __shfl_sync(0xffffffffu, be, 0);
            if (gt) { int p = bg + __popc(mg & lm); selu[p] = u; seli[p] = i; }
            if (eq) { int p = be + __popc(me & lm); cu[p] = u; ci[p] = i; }
        }
        need = nneed;
    }
    __syncthreads();

    // ---- levels 2-4 on compacted candidates ----
    uint32_t* su = cu; int* si = ci;
    uint32_t* tu = du; int* ti = di;
    for (int lev = 1; lev < 4; lev++) {
        int shift = 24 - 8*lev;
        hist[t] = 0;
        if (t == 0) nc2 = 0;
        __syncthreads();
        int ncl = nc;
        for (int i = t; i < ncl; i += 256) atomicAdd(&hist[(su[i] >> shift) & 0xFFu], 1u);
        __syncthreads();
        suffix_scan256(hist, Ssum, wtot, t, lane, w);
        if (Ssum[t] >= (uint32_t)need && Ssum[t+1] < (uint32_t)need) selbin = t;
        __syncthreads();
        uint32_t b = selbin;
        int nneed = need - (int)Ssum[b+1];
        int bound = (ncl + 255) & ~255;
        for (int i = t; i < bound; i += 256) {
            bool valid = i < ncl;
            uint32_t u = valid ? su[i] : 0u;
            uint32_t by = (u >> shift) & 0xFFu;
            bool gt = valid && by > b;
            bool eq = valid && by == b;
            uint32_t mg = __ballot_sync(0xffffffffu, gt);
            uint32_t me = __ballot_sync(0xffffffffu, eq);
            int bg = 0, be = 0;
            if (lane == 0) {
                if (mg) bg = atomicAdd(&selcnt, __popc(mg));
                if (me) be = atomicAdd(&nc2, __popc(me));
            }
            bg = __shfl_sync(0xffffffffu, bg, 0);
            be = __shfl_sync(0xffffffffu, be, 0);
            if (gt) { int p = bg + __popc(mg & lm); selu[p] = u; seli[p] = si[i]; }
            if (eq) { int p = be + __popc(me & lm); tu[p] = u; ti[p] = si[i]; }
        }
        __syncthreads();
        if (t == 0) nc = nc2;
        need = nneed;
        uint32_t* xu = su; su = tu; tu = xu;
        int* xi = si; si = ti; ti = xi;
        __syncthreads();
    }

    // ---- ties at exact threshold: lowest indices win ----
    {
        int ncf = nc, base = selcnt;
        for (int i = t; i < ncf; i += 256) {
            int mi_ = si[i];
            int r = 0;
            for (int j = 0; j < ncf; j++) if (si[j] < mi_) r++;
            if (r < need) { selu[base + r] = su[i]; seli[base + r] = mi_; }
        }
    }
    __syncthreads();

    // ---- rank sort 20 by (value desc, index asc), write in sorted order ----
    if (t < KK) {
        uint32_t mu_ = selu[t]; int mi_ = seli[t];
        int r = 0;
        #pragma unroll 4
        for (int j = 0; j < KK; j++) {
            uint32_t uj = selu[j]; int ij = seli[j];
            if (uj > mu_ || (uj == mu_ && ij < mi_)) r++;
        }
        g_idx[bn*KK + r] = mi_;
    }
}

// ---------------- per-point transform: g_uv[pt][r][0..2] = M[r] . X[pt][:, d] ---------
__global__ void transform_kernel(const float* __restrict__ X, int C, int CO) {
    extern __shared__ float sm[];
    int R = 4*CO;
    float* Ms = sm;
    float* Xs = sm + R*C;
    int t = threadIdx.x;
    int D3 = C*3;
    for (int i = t; i < R*C; i += 256) Ms[i] = g_M[i];
    int p0 = blockIdx.x * 16;
    for (int i = t; i < 16*D3; i += 256) Xs[i] = X[(size_t)p0*D3 + i];
    __syncthreads();
    for (int p = 0; p < 16; p++) {
        const float* xp = Xs + p*D3;
        for (int oi = t; oi < R*3; oi += 256) {
            int r = oi / 3, d = oi - r*3;
            const float* Mr = Ms + r*C;
            float acc = 0.f;
            for (int c = 0; c < C; c++) acc = fmaf(Mr[c], xp[c*3 + d], acc);
            g_uv[((size_t)(p0+p)*R + r)*4 + d] = acc;
        }
    }
}

// ---------------- mirrored norm helper: rounded squares, ascending adds --------------
__device__ __forceinline__ float mir_norm(float x, float y, float z) {
    float n2 = __fadd_rn(__fadd_rn(__fmul_rn(x,x), __fmul_rn(y,y)), __fmul_rn(z,z));
    return __fadd_rn(sqrtf(n2), VEPS);
}

// ---------------- BN stats over all edges (layers 1-4), Kahan fp32 + double atomics --
__global__ void statsA_kernel(int CO, int PTS) {
    int o = threadIdx.x;
    if (o >= CO) return;
    int R = 4*CO;
    int ptbase = (blockIdx.x * blockDim.y + threadIdx.y) * PTS;
    const float4* uvp = reinterpret_cast<const float4*>(g_uv);
    float s = 0.f, cs = 0.f, s2 = 0.f, cs2 = 0.f;
    for (int pp = 0; pp < PTS; pp++) {
        int pt = ptbase + pp;
        int b = pt >> 10;
        float4 v = uvp[(size_t)pt*R + CO + o];
        const int* nb = g_idx + pt*KK;
        for (int k = 0; k < KK; k++) {
            int j = b*NN + nb[k];
            float4 u = uvp[(size_t)j*R + o];
            float nrm = mir_norm(u.x + v.x, u.y + v.y, u.z + v.z);
            float y  = __fsub_rn(nrm, cs);
            float tt = __fadd_rn(s, y);
            cs = __fsub_rn(__fsub_rn(tt, s), y);
            s = tt;
            float q  = __fmul_rn(nrm, nrm);
            y  = __fsub_rn(q, cs2);
            tt = __fadd_rn(s2, y);
            cs2 = __fsub_rn(__fsub_rn(tt, s2), y);
            s2 = tt;
        }
    }
    atomicAdd(&g_sumd[o],   (double)s  - (double)cs);
    atomicAdd(&g_sumsqd[o], (double)s2 - (double)cs2);
}

__global__ void zero_stats() {
    int i = blockIdx.x*blockDim.x + threadIdx.x;
    if (i < 341) { g_sumd[i] = 0.0; g_sumsqd[i] = 0.0; }
}

__global__ void finalize_kernel(int CO, double inv_cnt) {
    int o = blockIdx.x*blockDim.x + threadIdx.x;
    if (o >= CO) return;
    double mu = g_sumd[o] * inv_cnt;
    double var = g_sumsqd[o] * inv_cnt - mu*mu;
    if (var < 0.0) var = 0.0;
    g_mu[o] = (float)mu;
    g_sf[o] = sqrtf(__fadd_rn((float)var, 1e-5f));
}

// ---------------- apply BN + VN-LeakyReLU + mean over k, mirrored ops ----------------
__global__ void passB_kernel(const float* __restrict__ gamma, const float* __restrict__ beta,
                             float* __restrict__ Xout, int CO) {
    int o = threadIdx.x;
    if (o >= CO) return;
    int R = 4*CO;
    int pt = blockIdx.x * blockDim.y + threadIdx.y;
    int b = pt >> 10;
    const float4* uvp = reinterpret_cast<const float4*>(g_uv);
    float4 v  = uvp[(size_t)pt*R + CO   + o];
    float4 dv = uvp[(size_t)pt*R + 3*CO + o];
    const int* nb = g_idx + pt*KK;
    float mu = g_mu[o], sf = g_sf[o], ga = gamma[o], be = beta[o];
    const float a1 = 0.2f, a2 = __fsub_rn(1.0f, 0.2f);
    float ax = 0.f, ay = 0.f, az = 0.f;
    for (int k = 0; k < KK; k++) {
        int j = b*NN + nb[k];
        float4 u  = uvp[(size_t)j*R + o];
        float4 du = uvp[(size_t)j*R + 2*CO + o];
        float px = u.x + v.x,  py = u.y + v.y,  pz = u.z + v.z;
        float dx = du.x + dv.x, dy = du.y + dv.y, dz = du.z + dv.z;
        float nrm = mir_norm(px, py, pz);
        float tbn = __fdiv_rn(__fsub_rn(nrm, mu), sf);
        float nbn = __fadd_rn(__fmul_rn(tbn, ga), be);
        float qx = __fmul_rn(__fdiv_rn(px, nrm), nbn);
        float qy = __fmul_rn(__fdiv_rn(py, nrm), nbn);
        float qz = __fmul_rn(__fdiv_rn(pz, nrm), nbn);
        float dot = __fadd_rn(__fadd_rn(__fmul_rn(qx,dx), __fmul_rn(qy,dy)), __fmul_rn(qz,dz));
        float ox, oy, oz;
        if (dot >= 0.f) { ox = qx; oy = qy; oz = qz; }
        else {
            float dsq = __fadd_rn(__fadd_rn(__fmul_rn(dx,dx), __fmul_rn(dy,dy)), __fmul_rn(dz,dz));
            float tt = __fdiv_rn(dot, __fadd_rn(dsq, VEPS));
            ox = __fsub_rn(qx, __fmul_rn(tt, dx));
            oy = __fsub_rn(qy, __fmul_rn(tt, dy));
            oz = __fsub_rn(qz, __fmul_rn(tt, dz));
        }
        ax = __fadd_rn(ax, __fadd_rn(__fmul_rn(a1,qx), __fmul_rn(a2,ox)));
        ay = __fadd_rn(ay, __fadd_rn(__fmul_rn(a1,qy), __fmul_rn(a2,oy)));
        az = __fadd_rn(az, __fadd_rn(__fmul_rn(a1,qz), __fmul_rn(a2,oz)));
    }
    float* op = Xout + ((size_t)pt*CO + o)*3;
    op[0] = __fdiv_rn(ax, 20.0f);
    op[1] = __fdiv_rn(ay, 20.0f);
    op[2] = __fdiv_rn(az, 20.0f);
}

// ---------------- layer 5 ----------------
__device__ __forceinline__ const float* cat_ptr(int pt, int c) {
    if (c < 21) return g_x1 + ((size_t)pt*21 + c)*3;
    if (c < 42) return g_x2 + ((size_t)pt*21 + (c-21))*3;
    if (c < 84) return g_x3 + ((size_t)pt*42 + (c-42))*3;
    return g_x4 + ((size_t)pt*85 + (c-84))*3;
}

// l5 GEMM v2 + folded dir row (virtual channel 341 -> g_d5v).
__global__ __launch_bounds__(256) void l5_gemm_kernel(const float* __restrict__ w5,
                                                      const float* __restrict__ d5,
                                                      float* __restrict__ out) {
    extern __shared__ float sm[];
    float* Ws = sm;               // [32][169]
    float* Cs = sm + 32*169;      // [169][96], col = d*32 + p
    int t = threadIdx.x;
    int ob = blockIdx.y * 32;
    int pb = blockIdx.x * 32;
    for (int i = t; i < 32*169; i += 256) {
        int o = i / 169, c = i - o*169;
        int og = ob + o;
        float wv = 0.f;
        if (og < 341) wv = w5[og*169 + c];
        else if (og == 341) wv = d5[c];
        Ws[i] = wv;
    }
    for (int i = t; i < 169*96; i += 256) {
        int c = i / 96, r = i - c*96;
        int d = r >> 5, p = r & 31;
        Cs[i] = cat_ptr(pb + p, c)[d];
    }
    __syncthreads();
    int wid = t >> 5, lane = t & 31;
    int b = pb >> 10;
    int nbase = pb & 1023;
    float acc[4][3];
    #pragma unroll
    for (int j = 0; j < 4; j++) { acc[j][0] = acc[j][1] = acc[j][2] = 0.f; }
    const float* w0p = Ws + (wid*4 + 0)*169;
    const float* w1p = Ws + (wid*4 + 1)*169;
    const float* w2p = Ws + (wid*4 + 2)*169;
    const float* w3p = Ws + (wid*4 + 3)*169;
    const float* cp = Cs + lane;
    for (int c = 0; c < 169; c++) {
        float x0 = cp[0], x1 = cp[32], x2 = cp[64];
        float wv0 = w0p[c], wv1 = w1p[c], wv2 = w2p[c], wv3 = w3p[c];
        acc[0][0] = fmaf(wv0, x0, acc[0][0]);
        acc[0][1] = fmaf(wv0, x1, acc[0][1]);
        acc[0][2] = fmaf(wv0, x2, acc[0][2]);
        acc[1][0] = fmaf(wv1, x0, acc[1][0]);
        acc[1][1] = fmaf(wv1, x1, acc[1][1]);
        acc[1][2] = fmaf(wv1, x2, acc[1][2]);
        acc[2][0] = fmaf(wv2, x0, acc[2][0]);
        acc[2][1] = fmaf(wv2, x1, acc[2][1]);
        acc[2][2] = fmaf(wv2, x2, acc[2][2]);
        acc[3][0] = fmaf(wv3, x0, acc[3][0]);
        acc[3][1] = fmaf(wv3, x1, acc[3][1]);
        acc[3][2] = fmaf(wv3, x2, acc[3][2]);
        cp += 96;
    }
    #pragma unroll
    for (int j = 0; j < 4; j++) {
        int og = ob + wid*4 + j;
        if (og < 341) {
            #pragma unroll
            for (int d = 0; d < 3; d++)
                out[(((size_t)b*341 + og)*3 + d)*NN + nbase + lane] = acc[j][d];
        } else if (og == 341) {
            #pragma unroll
            for (int d = 0; d < 3; d++)
                g_d5v[(b*3 + d)*NN + nbase + lane] = acc[j][d];
        }
    }
}

__global__ void l5_stats_kernel(const float* __restrict__ p) {
    int o = blockIdx.x, b = blockIdx.y, t = threadIdx.x;
    const float* base = p + ((size_t)b*341 + o)*3*NN;
    double s = 0.0, s2 = 0.0;
    for (int n = t; n < NN; n += 256) {
        float nrm = mir_norm(base[n], base[NN + n], base[2*NN + n]);
        s += (double)nrm; s2 = fma((double)nrm, (double)nrm, s2);
    }
    __shared__ double sh1[8], sh2[8];
    #pragma unroll
    for (int off = 16; off; off >>= 1) {
        s  += __shfl_down_sync(0xffffffffu, s,  off);
        s2 += __shfl_down_sync(0xffffffffu, s2, off);
    }
    if ((t & 31) == 0) { sh1[t >> 5] = s; sh2[t >> 5] = s2; }
    __syncthreads();
    if (t == 0) {
        double a = 0.0, a2 = 0.0;
        #pragma unroll
        for (int w = 0; w < 8; w++) { a += sh1[w]; a2 += sh2[w]; }
        atomicAdd(&g_sumd[o], a);
        atomicAdd(&g_sumsqd[o], a2);
    }
}

__global__ void l5_apply_kernel(float* __restrict__ p, const float* __restrict__ gamma,
                                const float* __restrict__ beta) {
    int o = blockIdx.x, b = blockIdx.y, t = threadIdx.x;
    float mu = g_mu[o], sf = g_sf[o], ga = gamma[o], be = beta[o];
    const float a1 = 0.2f, a2 = __fsub_rn(1.0f, 0.2f);
    float* base = p + ((size_t)b*341 + o)*3*NN;
    const float* db = g_d5v + b*3*NN;
    for (int n = t; n < NN; n += 256) {
        float x = base[n], y = base[NN + n], z = base[2*NN + n];
        float dx = db[n], dy = db[NN + n], dz = db[2*NN + n];
        float nrm = mir_norm(x, y, z);
        float tbn = __fdiv_rn(__fsub_rn(nrm, mu), sf);
        float nbn = __fadd_rn(__fmul_rn(tbn, ga), be);
        float qx = __fmul_rn(__fdiv_rn(x, nrm), nbn);
        float qy = __fmul_rn(__fdiv_rn(y, nrm), nbn);
        float qz = __fmul_rn(__fdiv_rn(z, nrm), nbn);
        float dot = __fadd_rn(__fadd_rn(__fmul_rn(qx,dx), __fmul_rn(qy,dy)), __fmul_rn(qz,dz));
        float ox, oy, oz;
        if (dot >= 0.f) { ox = qx; oy = qy; oz = qz; }
        else {
            float dsq = __fadd_rn(__fadd_rn(__fmul_rn(dx,dx), __fmul_rn(dy,dy)), __fmul_rn(dz,dz));
            float tt = __fdiv_rn(dot, __fadd_rn(dsq, VEPS));
            ox = __fsub_rn(qx, __fmul_rn(tt, dx));
            oy = __fsub_rn(qy, __fmul_rn(tt, dy));
            oz = __fsub_rn(qz, __fmul_rn(tt, dz));
        }
        base[n]      = __fadd_rn(__fmul_rn(a1,qx), __fmul_rn(a2,ox));
        base[NN+n]   = __fadd_rn(__fmul_rn(a1,qy), __fmul_rn(a2,oy));
        base[2*NN+n] = __fadd_rn(__fmul_rn(a1,qz), __fmul_rn(a2,oz));
    }
}

// ---------------- host orchestration ----------------
static void run_layer(const float* Xin, int C, int CO,
                      const float* w, const float* dw,
                      const float* gamma, const float* beta,
                      float* Xout) {
    int D = C*3;
    prep_kernel<<<BN/256, 256>>>(Xin, D, w, dw, C, CO);
    gram_kernel<<<dim3(16,8,8), 256>>>(Xin, D);
    topk_kernel<<<BN, 256>>>();
    int smem_t = (4*CO*C + 16*D) * 4;
    transform_kernel<<<BN/16, 256, smem_t>>>(Xin, C, CO);
    int COW = ((CO + 31)/32)*32;
    int PY = 256 / COW;
    dim3 blk(COW, PY);
    const int PTS = 8;
    statsA_kernel<<<BN/(PY*PTS), blk>>>(CO, PTS);
    finalize_kernel<<<(CO + 127)/128, 128>>>(CO, 1.0/((double)BN*KK));
    passB_kernel<<<BN/PY, blk>>>(gamma, beta, Xout, CO);
}

extern "C" void kernel_launch(void* const* d_in, const int* in_sizes, int n_in,
                              void* d_out, int out_size) {
    const float* x   = (const float*)d_in[0];
    const float* w1  = (const float*)d_in[1];
    const float* dd1 = (const float*)d_in[2];
    const float* gg1 = (const float*)d_in[3];
    const float* bb1 = (const float*)d_in[4];
    const float* w2  = (const float*)d_in[5];
    const float* dd2 = (const float*)d_in[6];
    const float* gg2 = (const float*)d_in[7];
    const float* bb2 = (const float*)d_in[8];
    const float* w3  = (const float*)d_in[9];
    const float* dd3 = (const float*)d_in[10];
    const float* gg3 = (const float*)d_in[11];
    const float* bb3 = (const float*)d_in[12];
    const float* w4  = (const float*)d_in[13];
    const float* dd4 = (const float*)d_in[14];
    const float* gg4 = (const float*)d_in[15];
    const float* bb4 = (const float*)d_in[16];
    const float* w5  = (const float*)d_in[17];
    const float* dd5 = (const float*)d_in[18];
    const float* gg5 = (const float*)d_in[19];
    const float* bb5 = (const float*)d_in[20];
    float* out = (float*)d_out;

    cudaFuncSetAttribute(transform_kernel, cudaFuncAttributeMaxDynamicSharedMemorySize, 70*1024);
    cudaFuncSetAttribute(l5_gemm_kernel,   cudaFuncAttributeMaxDynamicSharedMemorySize, 90*1024);

    float *px1, *px2, *px3, *px4;
    cudaGetSymbolAddress((void**)&px1, g_x1);
    cudaGetSymbolAddress((void**)&px2, g_x2);
    cudaGetSymbolAddress((void**)&px3, g_x3);
    cudaGetSymbolAddress((void**)&px4, g_x4);

    run_layer(x,   1,  21, w1, dd1, gg1, bb1, px1);
    run_layer(px1, 21, 21, w2, dd2, gg2, bb2, px2);
    run_layer(px2, 21, 42, w3, dd3, gg3, bb3, px3);
    run_layer(px3, 42, 85, w4, dd4, gg4, bb4, px4);

    // layer 5 (dir row folded into gemm as virtual channel 341)
    zero_stats<<<2, 256>>>();
    l5_gemm_kernel<<<dim3(BN/32, 11), 256, 86528>>>(w5, dd5, out);
    l5_stats_kernel<<<dim3(341, BB), 256>>>(out);
    finalize_kernel<<<(341 + 127)/128, 128>>>(341, 1.0/(double)BN);
    l5_apply_kernel<<<dim3(341, BB), 256>>>(out, gg5, bb5);
}